// round 8
// baseline (speedup 1.0000x reference)
#include <cuda_runtime.h>
#include <math.h>

// ---------------------------------------------------------------------------
// ArticulatoryVQTokenizer fused kernel (sm_100a).
// Encoder/decoder: exact fp32 + f32x2 packed FMA (unchanged, bit-exact).
// VQ: tf32 mma.sync screen over all 512 codes + exact fp32 rescore of the
//     margin set; per-token (d2bits<<32|code) atomicMin reproduces XLA argmin
//     semantics exactly and deterministically.
// Outputs (float32): [0,1835008) recon | [1835008,1966080) indices |
//   [1966080] commit_loss | [1966081] perplexity
// ---------------------------------------------------------------------------

#define TPB        256
#define NWARP      8
#define NTOK       131072
#define NTASK      4096              // 32-token warp tasks
#define GRID_A     148
#define KCODES     512
#define LATENT     64
#define HID        128
#define INDIM      14

#define OUT_IDX_OFF   1835008
#define OUT_COMMIT    1966080
#define OUT_PERP      1966081

// smem layout (float offsets) — same block footprint as R5/R7
#define OFF_W1P   0                      // 2048
#define OFF_W2    2048                   // 8192
#define OFF_DW1P  10240                  // 8192
#define OFF_DW2T  18432                  // 2048
#define OFF_EB1   20480                  // 128
#define OFF_LN1G  20608
#define OFF_LN1B  20736
#define OFF_B2    20864                  // 64
#define OFF_DB1   20928
#define OFF_LN2G  21056
#define OFF_LN2B  21184
#define OFF_DB2   21312                  // 16
#define OFF_CC    21328                  // 512
#define OFF_HIST  21840                  // 512 ints
#define OFF_CHUNK 22352                  // 8 warps * 256 floats scratch
#define OFF_H     24400                  // 128*256 thread-major (enc/dec + Z)
#define SMEM_FLOATS (OFF_H + HID * TPB)  // 57168
#define SMEM_BYTES  (SMEM_FLOATS * 4)    // 228672

typedef unsigned long long u64;
typedef unsigned int u32;

__device__ int          g_counts[KCODES];
__device__ float        g_taskc[NTASK];
__device__ unsigned int g_ticket = 0;
__device__ unsigned int g_done = 0;
// tf32 pre-fragmented codebook: entry e=(n*8+s)*32+lane holds {lo=B[k0][n8],hi=B[k0+4][n8]}
__device__ __align__(16) u64 g_cbf[64 * 8 * 32];

__device__ __forceinline__ u64 pk2(float lo, float hi) {
    u64 r; asm("mov.b64 %0, {%1, %2};" : "=l"(r) : "f"(lo), "f"(hi)); return r;
}
__device__ __forceinline__ void up2(u64 v, float& lo, float& hi) {
    asm("mov.b64 {%0, %1}, %2;" : "=f"(lo), "=f"(hi) : "l"(v));
}
__device__ __forceinline__ u64 f2fma(u64 a, u64 b, u64 c) {
    u64 d; asm("fma.rn.f32x2 %0, %1, %2, %3;" : "=l"(d) : "l"(a), "l"(b), "l"(c));
    return d;
}
__device__ __forceinline__ u32 cvt_tf32(float f) {
    u32 r; asm("cvt.rna.tf32.f32 %0, %1;" : "=r"(r) : "f"(f)); return r;
}
__device__ __forceinline__ void mma_tf32(float& d0, float& d1, float& d2, float& d3,
                                         u32 a0, u32 a1, u32 a2, u32 a3,
                                         u32 b0, u32 b1) {
    asm("mma.sync.aligned.m16n8k8.row.col.f32.tf32.tf32.f32 "
        "{%0,%1,%2,%3}, {%4,%5,%6,%7}, {%8,%9}, {%0,%1,%2,%3};"
        : "+f"(d0), "+f"(d1), "+f"(d2), "+f"(d3)
        : "r"(a0), "r"(a1), "r"(a2), "r"(a3), "r"(b0), "r"(b1));
}

// gelu exact, matching jax: 0.5 * x * (1 + erf(x / sqrt(2)))
__device__ __forceinline__ float gelu_exact(float t) {
    float u = __fdiv_rn(t, 1.41421356237309515f);
    float e = erff(u);
    return __fmul_rn(__fmul_rn(0.5f, t), __fadd_rn(1.0f, e));
}

// ---------------------------------------------------------------------------
// prep: build tf32 B-fragment codebook
__global__ void vq_prep_kernel(const float* __restrict__ cb) {
    int e = blockIdx.x * blockDim.x + threadIdx.x;   // 32*512 = 16384
    int lane = e & 31;
    int s = (e >> 5) & 7;
    int n = e >> 8;
    int code = n * 8 + (lane >> 2);
    int k0 = s * 8 + (lane & 3);
    u32 lo = cvt_tf32(cb[code * 64 + k0]);
    u32 hi = cvt_tf32(cb[code * 64 + k0 + 4]);
    g_cbf[e] = ((u64)hi << 32) | (u64)lo;
}

// ---------------------------------------------------------------------------
// Exact rescore of one (token, code): sequential-k fp32 chain (XLA order),
// fold into per-token atomicMin key.
__device__ __noinline__ void rescore(const float* __restrict__ sm, int wid, int tl,
                                     int code, const float* __restrict__ CB,
                                     u64* __restrict__ BESTp) {
    const float* zcol = sm + OFF_H + wid * 32 + tl;
    const float* cp = CB + code * 64;
    float dot = 0.f;
#pragma unroll 8
    for (int k = 0; k < 64; k++) dot = fmaf(zcol[k * TPB], __ldg(cp + k), dot);
    float zzt = sm[OFF_CHUNK + wid * 256 + tl];
    float d2e = __fadd_rn(__fsub_rn(zzt, __fmul_rn(2.f, dot)), sm[OFF_CC + code]);
    u32 ob = __float_as_uint(d2e);
    ob = (ob & 0x80000000u) ? ~ob : (ob | 0x80000000u);
    u64 key = ((u64)ob << 32) | (u32)code;
    atomicMin((unsigned long long*)(BESTp + tl), (unsigned long long)key);
}

// ---------------------------------------------------------------------------
// Encoder for one token: z[64] out. Identical arithmetic to R5/R7.
__device__ __forceinline__ void encode_token(
    float* sm, int tid, const float* __restrict__ X, int tok, float* z)
{
    const float inv128 = 0.0078125f;
    float xr[INDIM];
    const float* xp = X + (size_t)tok * INDIM;
#pragma unroll
    for (int i = 0; i < INDIM; i++) xr[i] = __ldg(xp + i);
    u64 xd[INDIM];
#pragma unroll
    for (int i = 0; i < INDIM; i++) xd[i] = pk2(xr[i], xr[i]);

    float sum = 0.f;
#pragma unroll 2
    for (int g = 0; g < 32; g++) {
        const ulonglong2* w0 = (const ulonglong2*)(sm + OFF_W1P + (2 * g) * 32);
        const ulonglong2* w1 = (const ulonglong2*)(sm + OFF_W1P + (2 * g + 1) * 32);
        u64 a0 = 0ull, a1 = 0ull;
#pragma unroll
        for (int ii = 0; ii < 7; ii++) {
            ulonglong2 u0 = w0[ii], u1 = w1[ii];
            a0 = f2fma(xd[2 * ii], u0.x, a0);
            a0 = f2fma(xd[2 * ii + 1], u0.y, a0);
            a1 = f2fma(xd[2 * ii], u1.x, a1);
            a1 = f2fma(xd[2 * ii + 1], u1.y, a1);
        }
        float h0, h1, h2, h3;
        up2(a0, h0, h1); up2(a1, h2, h3);
        h0 = __fadd_rn(h0, sm[OFF_EB1 + 4 * g + 0]);
        h1 = __fadd_rn(h1, sm[OFF_EB1 + 4 * g + 1]);
        h2 = __fadd_rn(h2, sm[OFF_EB1 + 4 * g + 2]);
        h3 = __fadd_rn(h3, sm[OFF_EB1 + 4 * g + 3]);
        sum = __fadd_rn(__fadd_rn(__fadd_rn(__fadd_rn(sum, h0), h1), h2), h3);
        sm[OFF_H + (4 * g + 0) * TPB + tid] = h0;
        sm[OFF_H + (4 * g + 1) * TPB + tid] = h1;
        sm[OFF_H + (4 * g + 2) * TPB + tid] = h2;
        sm[OFF_H + (4 * g + 3) * TPB + tid] = h3;
    }
    float mu = __fmul_rn(sum, inv128);
    float vs = 0.f;
#pragma unroll 4
    for (int j = 0; j < HID; j++) {
        float d = __fsub_rn(sm[OFF_H + j * TPB + tid], mu);
        vs = __fadd_rn(vs, __fmul_rn(d, d));
    }
    float var = __fmul_rn(vs, inv128);
    float rs = __fdiv_rn(1.0f, sqrtf(__fadd_rn(var, 1e-5f)));

    u64 zp[32];
#pragma unroll
    for (int t2 = 0; t2 < 32; t2++) zp[t2] = 0ull;
#pragma unroll 2
    for (int j = 0; j < HID; j++) {
        float h = sm[OFF_H + j * TPB + tid];
        float t = __fadd_rn(__fmul_rn(__fmul_rn(__fsub_rn(h, mu), rs), sm[OFF_LN1G + j]), sm[OFF_LN1B + j]);
        float gel = gelu_exact(t);
        u64 ag = pk2(gel, gel);
        const ulonglong2* wv = (const ulonglong2*)(sm + OFF_W2 + j * LATENT);
#pragma unroll
        for (int t2 = 0; t2 < 16; t2++) {
            ulonglong2 u = wv[t2];
            zp[2 * t2]     = f2fma(ag, u.x, zp[2 * t2]);
            zp[2 * t2 + 1] = f2fma(ag, u.y, zp[2 * t2 + 1]);
        }
    }
#pragma unroll
    for (int t2 = 0; t2 < 32; t2++) up2(zp[t2], z[2 * t2], z[2 * t2 + 1]);
#pragma unroll
    for (int k = 0; k < LATENT; k++) z[k] = __fadd_rn(z[k], sm[OFF_B2 + k]);
}

// ---------------------------------------------------------------------------
// Decoder for one token from z[64]; returns commit partial. R5/R7 arithmetic.
__device__ __forceinline__ float decode_token(
    float* sm, int tid, const float* __restrict__ CB, int tok, int bidx,
    const float* z, float* __restrict__ out)
{
    const float inv128 = 0.0078125f;
    float qst[LATENT];
    float closs = 0.f;
    const float4* qp = (const float4*)(CB + (size_t)bidx * LATENT);
#pragma unroll
    for (int k4 = 0; k4 < 16; k4++) {
        float4 f = __ldg(qp + k4);
        float qv[4] = {f.x, f.y, f.z, f.w};
#pragma unroll
        for (int u = 0; u < 4; u++) {
            int k = 4 * k4 + u;
            float dqz = __fsub_rn(qv[u], z[k]);
            closs = __fadd_rn(closs, __fmul_rn(dqz, dqz));
            qst[k] = __fadd_rn(z[k], dqz);
        }
    }

    float sum = 0.f;
#pragma unroll 1
    for (int g = 0; g < 32; g++) {
        const ulonglong2* w0 = (const ulonglong2*)(sm + OFF_DW1P + (2 * g) * 128);
        const ulonglong2* w1 = (const ulonglong2*)(sm + OFF_DW1P + (2 * g + 1) * 128);
        u64 a0 = 0ull, a1 = 0ull;
#pragma unroll
        for (int kk = 0; kk < 32; kk++) {
            ulonglong2 u0 = w0[kk], u1 = w1[kk];
            u64 q0 = pk2(qst[2 * kk], qst[2 * kk]);
            u64 q1 = pk2(qst[2 * kk + 1], qst[2 * kk + 1]);
            a0 = f2fma(q0, u0.x, a0);
            a0 = f2fma(q1, u0.y, a0);
            a1 = f2fma(q0, u1.x, a1);
            a1 = f2fma(q1, u1.y, a1);
        }
        float h0, h1, h2, h3;
        up2(a0, h0, h1); up2(a1, h2, h3);
        h0 = __fadd_rn(h0, sm[OFF_DB1 + 4 * g + 0]);
        h1 = __fadd_rn(h1, sm[OFF_DB1 + 4 * g + 1]);
        h2 = __fadd_rn(h2, sm[OFF_DB1 + 4 * g + 2]);
        h3 = __fadd_rn(h3, sm[OFF_DB1 + 4 * g + 3]);
        sum = __fadd_rn(__fadd_rn(__fadd_rn(__fadd_rn(sum, h0), h1), h2), h3);
        sm[OFF_H + (4 * g + 0) * TPB + tid] = h0;
        sm[OFF_H + (4 * g + 1) * TPB + tid] = h1;
        sm[OFF_H + (4 * g + 2) * TPB + tid] = h2;
        sm[OFF_H + (4 * g + 3) * TPB + tid] = h3;
    }
    float mu2 = __fmul_rn(sum, inv128);
    float vs2 = 0.f;
#pragma unroll 4
    for (int j = 0; j < HID; j++) {
        float d = __fsub_rn(sm[OFF_H + j * TPB + tid], mu2);
        vs2 = __fadd_rn(vs2, __fmul_rn(d, d));
    }
    float var2 = __fmul_rn(vs2, inv128);
    float rs2 = __fdiv_rn(1.0f, sqrtf(__fadd_rn(var2, 1e-5f)));

    u64 op[7];
#pragma unroll
    for (int i = 0; i < 7; i++) op[i] = 0ull;
#pragma unroll 2
    for (int j = 0; j < HID; j++) {
        float h = sm[OFF_H + j * TPB + tid];
        float t = __fadd_rn(__fmul_rn(__fmul_rn(__fsub_rn(h, mu2), rs2), sm[OFF_LN2G + j]), sm[OFF_LN2B + j]);
        float gel = gelu_exact(t);
        u64 ag = pk2(gel, gel);
        const ulonglong2* rv = (const ulonglong2*)(sm + OFF_DW2T + j * 16);
        ulonglong2 u0 = rv[0], u1 = rv[1], u2 = rv[2], u3 = rv[3];
        op[0] = f2fma(ag, u0.x, op[0]);
        op[1] = f2fma(ag, u0.y, op[1]);
        op[2] = f2fma(ag, u1.x, op[2]);
        op[3] = f2fma(ag, u1.y, op[3]);
        op[4] = f2fma(ag, u2.x, op[4]);
        op[5] = f2fma(ag, u2.y, op[5]);
        op[6] = f2fma(ag, u3.x, op[6]);
    }
    float o[14];
#pragma unroll
    for (int i = 0; i < 7; i++) up2(op[i], o[2 * i], o[2 * i + 1]);
    float* opo = out + (size_t)tok * INDIM;
#pragma unroll
    for (int i = 0; i < INDIM; i++) opo[i] = __fadd_rn(o[i], sm[OFF_DB2 + i]);
    return closs;
}

// ---------------------------------------------------------------------------
__global__ void __launch_bounds__(TPB, 1)
vq_fused_kernel(const float* __restrict__ X,
                const float* __restrict__ EW1, const float* __restrict__ EB1,
                const float* __restrict__ L1G, const float* __restrict__ L1B,
                const float* __restrict__ EW2, const float* __restrict__ EB2,
                const float* __restrict__ CB,
                const float* __restrict__ DW1, const float* __restrict__ DB1,
                const float* __restrict__ L2G, const float* __restrict__ L2B,
                const float* __restrict__ DW2, const float* __restrict__ DB2,
                float* __restrict__ out) {
    extern __shared__ float sm[];
    int* sHist = (int*)(sm + OFF_HIST);

    const int tid  = threadIdx.x;
    const int wid  = tid >> 5;
    const int lane = tid & 31;
    const int g    = lane >> 2;     // groupID
    const int tig  = lane & 3;      // threadID in group

    // ---- one-time block init ----
    for (int idx = tid; idx < 64 * 32; idx += TPB) {
        int p = idx >> 5, r = idx & 31, i = r >> 1, s = r & 1;
        sm[OFF_W1P + idx] = (i < INDIM) ? EW1[i * HID + 2 * p + s] : 0.f;
    }
    for (int i = tid; i < HID * LATENT; i += TPB) sm[OFF_W2 + i] = EW2[i];
    for (int idx = tid; idx < 64 * 128; idx += TPB) {
        int p = idx >> 7, r = idx & 127, k = r >> 1, s = r & 1;
        sm[OFF_DW1P + idx] = DW1[k * HID + 2 * p + s];
    }
    for (int i = tid; i < HID * INDIM; i += TPB) {
        int r = i / INDIM, c = i % INDIM;
        sm[OFF_DW2T + r * 16 + c] = DW2[i];
    }
    for (int i = tid; i < HID; i += TPB) { sm[OFF_DW2T + i * 16 + 14] = 0.f; sm[OFF_DW2T + i * 16 + 15] = 0.f; }
    for (int i = tid; i < HID; i += TPB) {
        sm[OFF_EB1 + i] = EB1[i]; sm[OFF_LN1G + i] = L1G[i]; sm[OFF_LN1B + i] = L1B[i];
        sm[OFF_DB1 + i] = DB1[i]; sm[OFF_LN2G + i] = L2G[i]; sm[OFF_LN2B + i] = L2B[i];
    }
    for (int i = tid; i < LATENT; i += TPB) sm[OFF_B2 + i] = EB2[i];
    for (int i = tid; i < 16; i += TPB) sm[OFF_DB2 + i] = (i < INDIM) ? DB2[i] : 0.f;
    for (int i = tid; i < KCODES; i += TPB) sHist[i] = 0;
    for (int c = tid; c < KCODES; c += TPB) {
        const float* p = CB + c * LATENT;
        float acc = 0.f;
#pragma unroll
        for (int k = 0; k < LATENT; k++) {
            float v = __ldg(p + k);
            acc = __fadd_rn(acc, __fmul_rn(v, v));
        }
        sm[OFF_CC + c] = acc;
    }
    __syncthreads();

    // max codebook norm (for rigorous tf32 error margin)
    float cn = 0.f;
    for (int i = 0; i < KCODES; i++) cn = fmaxf(cn, sm[OFF_CC + i]);
    const float cnmax = sqrtf(cn);

    float* ZZp = sm + OFF_CHUNK + wid * 256;          // [32] exact ||z||^2
    u64*   BESTp = (u64*)(sm + OFF_CHUNK + wid * 256 + 32);  // [32] u64 keys

    // ---- dynamic ticket loop: task = 32 tokens (token = lane) ----
    for (;;) {
        unsigned int t;
        if (lane == 0) t = atomicAdd(&g_ticket, 1u);
        t = __shfl_sync(0xffffffffu, t, 0);
        if (t >= NTASK) break;
        const int tok = (int)t * 32 + lane;

        // ---- encode; stash exact z into H rows 0..63 (H free until decode)
        float z[LATENT];
        encode_token(sm, tid, X, tok, z);
        float zz = 0.f;
#pragma unroll
        for (int k = 0; k < LATENT; k++) zz = __fadd_rn(zz, __fmul_rn(z[k], z[k]));
#pragma unroll
        for (int k = 0; k < LATENT; k++) sm[OFF_H + k * TPB + tid] = z[k];
        ZZp[lane] = zz;
        ((unsigned long long*)BESTp)[lane] = 0xFFFFFFFFFFFFFFFFull;
        __syncwarp();

        // ---- build tf32 A fragments from the warp's Z slab ----
        // Zr(r,k) = sm[OFF_H + k*TPB + wid*32 + r]
        u32 A0[32], A1[32];
#pragma unroll
        for (int s = 0; s < 8; s++) {
            A0[4 * s + 0] = cvt_tf32(sm[OFF_H + (8 * s + tig) * TPB + wid * 32 + g]);
            A0[4 * s + 1] = cvt_tf32(sm[OFF_H + (8 * s + tig) * TPB + wid * 32 + g + 8]);
            A0[4 * s + 2] = cvt_tf32(sm[OFF_H + (8 * s + tig + 4) * TPB + wid * 32 + g]);
            A0[4 * s + 3] = cvt_tf32(sm[OFF_H + (8 * s + tig + 4) * TPB + wid * 32 + g + 8]);
            A1[4 * s + 0] = cvt_tf32(sm[OFF_H + (8 * s + tig) * TPB + wid * 32 + g + 16]);
            A1[4 * s + 1] = cvt_tf32(sm[OFF_H + (8 * s + tig) * TPB + wid * 32 + g + 24]);
            A1[4 * s + 2] = cvt_tf32(sm[OFF_H + (8 * s + tig + 4) * TPB + wid * 32 + g + 16]);
            A1[4 * s + 3] = cvt_tf32(sm[OFF_H + (8 * s + tig + 4) * TPB + wid * 32 + g + 24]);
        }
        float zz0 = ZZp[g], zz1 = ZZp[g + 8], zz2 = ZZp[g + 16], zz3 = ZZp[g + 24];

        // ---- pass 1: approx min over all 512 codes ----
        float m0 = 3.4e38f, m1 = 3.4e38f, m2 = 3.4e38f, m3 = 3.4e38f;
        {
            u64 bc[8];
#pragma unroll
            for (int j = 0; j < 8; j++) bc[j] = __ldg((const u64*)g_cbf + j * 32 + lane);
#pragma unroll 1
            for (int n = 0; n < 64; n++) {
                u64 bn[8];
                if (n < 63) {
#pragma unroll
                    for (int j = 0; j < 8; j++)
                        bn[j] = __ldg((const u64*)g_cbf + (n + 1) * 256 + j * 32 + lane);
                }
                float dA0 = 0.f, dA1 = 0.f, dA2 = 0.f, dA3 = 0.f;
                float dB0 = 0.f, dB1 = 0.f, dB2 = 0.f, dB3 = 0.f;
#pragma unroll
                for (int s = 0; s < 8; s++) {
                    u32 b0 = (u32)bc[s], b1 = (u32)(bc[s] >> 32);
                    mma_tf32(dA0, dA1, dA2, dA3, A0[4*s], A0[4*s+1], A0[4*s+2], A0[4*s+3], b0, b1);
                    mma_tf32(dB0, dB1, dB2, dB3, A1[4*s], A1[4*s+1], A1[4*s+2], A1[4*s+3], b0, b1);
                }
                float cc0 = sm[OFF_CC + 8 * n + 2 * tig];
                float cc1 = sm[OFF_CC + 8 * n + 2 * tig + 1];
                m0 = fminf(m0, fminf(zz0 - 2.f * dA0 + cc0, zz0 - 2.f * dA1 + cc1));
                m1 = fminf(m1, fminf(zz1 - 2.f * dA2 + cc0, zz1 - 2.f * dA3 + cc1));
                m2 = fminf(m2, fminf(zz2 - 2.f * dB0 + cc0, zz2 - 2.f * dB1 + cc1));
                m3 = fminf(m3, fminf(zz3 - 2.f * dB2 + cc0, zz3 - 2.f * dB3 + cc1));
                if (n < 63) {
#pragma unroll
                    for (int j = 0; j < 8; j++) bc[j] = bn[j];
                }
            }
        }
        // quad-reduce mins (lanes of a quad share the same 4 rows)
        m0 = fminf(m0, __shfl_xor_sync(0xffffffffu, m0, 1));
        m0 = fminf(m0, __shfl_xor_sync(0xffffffffu, m0, 2));
        m1 = fminf(m1, __shfl_xor_sync(0xffffffffu, m1, 1));
        m1 = fminf(m1, __shfl_xor_sync(0xffffffffu, m1, 2));
        m2 = fminf(m2, __shfl_xor_sync(0xffffffffu, m2, 1));
        m2 = fminf(m2, __shfl_xor_sync(0xffffffffu, m2, 2));
        m3 = fminf(m3, __shfl_xor_sync(0xffffffffu, m3, 1));
        m3 = fminf(m3, __shfl_xor_sync(0xffffffffu, m3, 2));
        // thresholds: margin = 2^-6 * ||z|| * maxc||c|| + 1e-3 (>= 8x tf32 bound)
        float thr0 = m0 + 0.015625f * sqrtf(zz0) * cnmax + 1e-3f;
        float thr1 = m1 + 0.015625f * sqrtf(zz1) * cnmax + 1e-3f;
        float thr2 = m2 + 0.015625f * sqrtf(zz2) * cnmax + 1e-3f;
        float thr3 = m3 + 0.015625f * sqrtf(zz3) * cnmax + 1e-3f;

        // ---- pass 2: screen + exact rescore of margin set ----
        {
            u64 bc[8];
#pragma unroll
            for (int j = 0; j < 8; j++) bc[j] = __ldg((const u64*)g_cbf + j * 32 + lane);
#pragma unroll 1
            for (int n = 0; n < 64; n++) {
                u64 bn[8];
                if (n < 63) {
#pragma unroll
                    for (int j = 0; j < 8; j++)
                        bn[j] = __ldg((const u64*)g_cbf + (n + 1) * 256 + j * 32 + lane);
                }
                float dA0 = 0.f, dA1 = 0.f, dA2 = 0.f, dA3 = 0.f;
                float dB0 = 0.f, dB1 = 0.f, dB2 = 0.f, dB3 = 0.f;
#pragma unroll
                for (int s = 0; s < 8; s++) {
                    u32 b0 = (u32)bc[s], b1 = (u32)(bc[s] >> 32);
                    mma_tf32(dA0, dA1, dA2, dA3, A0[4*s], A0[4*s+1], A0[4*s+2], A0[4*s+3], b0, b1);
                    mma_tf32(dB0, dB1, dB2, dB3, A1[4*s], A1[4*s+1], A1[4*s+2], A1[4*s+3], b0, b1);
                }
                float cc0 = sm[OFF_CC + 8 * n + 2 * tig];
                float cc1 = sm[OFF_CC + 8 * n + 2 * tig + 1];
                int c0 = 8 * n + 2 * tig, c1 = c0 + 1;
                if (zz0 - 2.f * dA0 + cc0 <= thr0) rescore(sm, wid, g,      c0, CB, BESTp);
                if (zz0 - 2.f * dA1 + cc1 <= thr0) rescore(sm, wid, g,      c1, CB, BESTp);
                if (zz1 - 2.f * dA2 + cc0 <= thr1) rescore(sm, wid, g + 8,  c0, CB, BESTp);
                if (zz1 - 2.f * dA3 + cc1 <= thr1) rescore(sm, wid, g + 8,  c1, CB, BESTp);
                if (zz2 - 2.f * dB0 + cc0 <= thr2) rescore(sm, wid, g + 16, c0, CB, BESTp);
                if (zz2 - 2.f * dB1 + cc1 <= thr2) rescore(sm, wid, g + 16, c1, CB, BESTp);
                if (zz3 - 2.f * dB2 + cc0 <= thr3) rescore(sm, wid, g + 24, c0, CB, BESTp);
                if (zz3 - 2.f * dB3 + cc1 <= thr3) rescore(sm, wid, g + 24, c1, CB, BESTp);
                if (n < 63) {
#pragma unroll
                    for (int j = 0; j < 8; j++) bc[j] = bn[j];
                }
            }
        }
        __syncwarp();
        int bidx = (int)(((unsigned long long*)BESTp)[lane] & 0xFFFFFFFFull);

        atomicAdd(&sHist[bidx], 1);
        out[OUT_IDX_OFF + tok] = (float)bidx;

        // ---- reload exact z (H rows 0..63 of own column) and decode ----
#pragma unroll
        for (int k = 0; k < LATENT; k++) z[k] = sm[OFF_H + k * TPB + tid];
        float cl = decode_token(sm, tid, CB, tok, bidx, z, out);

        // per-task deterministic commit partial (fixed shfl tree)
#pragma unroll
        for (int s = 16; s > 0; s >>= 1)
            cl = __fadd_rn(cl, __shfl_down_sync(0xffffffffu, cl, s));
        if (lane == 0) g_taskc[t] = cl;
    }

    // ---- merge histogram ----
    __syncthreads();
    for (int i = tid; i < KCODES; i += TPB) {
        int c = sHist[i];
        if (c) atomicAdd(&g_counts[i], c);
    }

    // ---- last-block finalize ----
    __threadfence();
    __shared__ unsigned int sTicket;
    if (tid == 0) sTicket = atomicAdd(&g_done, 1u);
    __syncthreads();
    if (sTicket == GRID_A - 1) {
        float* sRed = sm + OFF_CHUNK;
        float s16 = 0.f;
#pragma unroll
        for (int j = 0; j < 16; j++) s16 += g_taskc[tid * 16 + j];
        float p0 = (float)g_counts[tid] * (1.0f / (float)NTOK);
        float p1 = (float)g_counts[tid + 256] * (1.0f / (float)NTOK);
        float ent = p0 * logf(p0 + 1e-10f) + p1 * logf(p1 + 1e-10f);
        sRed[tid] = s16;
        sRed[256 + tid] = ent;
        __syncthreads();
#pragma unroll
        for (int s = 128; s > 0; s >>= 1) {
            if (tid < s) {
                sRed[tid] += sRed[tid + s];
                sRed[256 + tid] += sRed[256 + tid + s];
            }
            __syncthreads();
        }
        if (tid == 0) {
            out[OUT_COMMIT] = 0.25f * (sRed[0] / ((float)NTOK * (float)LATENT));
            out[OUT_PERP] = expf(-sRed[256]);
        }
        __syncthreads();
        for (int i = tid; i < KCODES; i += TPB) g_counts[i] = 0;
        if (tid == 0) { g_done = 0; g_ticket = 0; }
    }
}

// ---------------------------------------------------------------------------
extern "C" void kernel_launch(void* const* d_in, const int* in_sizes, int n_in,
                              void* d_out, int out_size) {
    const float* x    = (const float*)d_in[0];
    const float* ew1  = (const float*)d_in[1];
    const float* eb1  = (const float*)d_in[2];
    const float* l1g  = (const float*)d_in[3];
    const float* l1b  = (const float*)d_in[4];
    const float* ew2  = (const float*)d_in[5];
    const float* eb2  = (const float*)d_in[6];
    const float* cb   = (const float*)d_in[7];
    const float* dw1  = (const float*)d_in[8];
    const float* db1  = (const float*)d_in[9];
    const float* l2g  = (const float*)d_in[10];
    const float* l2b  = (const float*)d_in[11];
    const float* dw2  = (const float*)d_in[12];
    const float* db2  = (const float*)d_in[13];
    float* out = (float*)d_out;

    cudaFuncSetAttribute(vq_fused_kernel,
                         cudaFuncAttributeMaxDynamicSharedMemorySize, SMEM_BYTES);

    vq_prep_kernel<<<32, 512>>>(cb);
    vq_fused_kernel<<<GRID_A, TPB, SMEM_BYTES>>>(
        x, ew1, eb1, l1g, l1b, ew2, eb2, cb,
        dw1, db1, l2g, l2b, dw2, db2, out);
}

// round 9
// speedup vs baseline: 1.3355x; 1.3355x over previous
#include <cuda_runtime.h>
#include <math.h>

// ---------------------------------------------------------------------------
// ArticulatoryVQTokenizer fused kernel (sm_100a).
// Encoder/decoder: exact fp32 + f32x2 packed FMA (bit-exact, unchanged).
// VQ: tf32 mma screen with best-2 tracking; provably-exact singleton fast
//     path (no rescore); batched per-lane exact rescore of margin sets.
// Outputs (float32): [0,1835008) recon | [1835008,1966080) indices |
//   [1966080] commit_loss | [1966081] perplexity
// ---------------------------------------------------------------------------

#define TPB        256
#define NWARP      8
#define NTOK       131072
#define NTASK      4096              // 32-token warp tasks
#define GRID_A     148
#define KCODES     512
#define LATENT     64
#define HID        128
#define INDIM      14

#define OUT_IDX_OFF   1835008
#define OUT_COMMIT    1966080
#define OUT_PERP      1966081

// smem layout (float offsets)
#define OFF_W1P   0                      // 2048
#define OFF_W2    2048                   // 8192
#define OFF_DW1P  10240                  // 8192
#define OFF_DW2T  18432                  // 2048
#define OFF_EB1   20480                  // 128
#define OFF_LN1G  20608
#define OFF_LN1B  20736
#define OFF_B2    20864                  // 64
#define OFF_DB1   20928
#define OFF_LN2G  21056
#define OFF_LN2B  21184
#define OFF_DB2   21312                  // 16
#define OFF_CC    21328                  // 512
#define OFF_HIST  21840                  // 512 ints
#define OFF_CHUNK 22352                  // 8 warps * 256 floats scratch
#define OFF_H     24400                  // 128*256 thread-major (enc/dec + Z + lists)
#define SMEM_FLOATS (OFF_H + HID * TPB)  // 57168
#define SMEM_BYTES  (SMEM_FLOATS * 4)    // 228672

typedef unsigned long long u64;
typedef unsigned int u32;

__device__ int          g_counts[KCODES];
__device__ float        g_taskc[NTASK];
__device__ unsigned int g_ticket = 0;
__device__ unsigned int g_done = 0;
// tf32 pre-fragmented codebook: entry e=(n*8+s)*32+lane holds {lo=B[k0][n8],hi=B[k0+4][n8]}
__device__ __align__(16) u64 g_cbf[64 * 8 * 32];

__device__ __forceinline__ u64 pk2(float lo, float hi) {
    u64 r; asm("mov.b64 %0, {%1, %2};" : "=l"(r) : "f"(lo), "f"(hi)); return r;
}
__device__ __forceinline__ void up2(u64 v, float& lo, float& hi) {
    asm("mov.b64 {%0, %1}, %2;" : "=f"(lo), "=f"(hi) : "l"(v));
}
__device__ __forceinline__ u64 f2fma(u64 a, u64 b, u64 c) {
    u64 d; asm("fma.rn.f32x2 %0, %1, %2, %3;" : "=l"(d) : "l"(a), "l"(b), "l"(c));
    return d;
}
__device__ __forceinline__ u32 cvt_tf32(float f) {
    u32 r; asm("cvt.rna.tf32.f32 %0, %1;" : "=r"(r) : "f"(f)); return r;
}
__device__ __forceinline__ void mma_tf32(float& d0, float& d1, float& d2, float& d3,
                                         u32 a0, u32 a1, u32 a2, u32 a3,
                                         u32 b0, u32 b1) {
    asm("mma.sync.aligned.m16n8k8.row.col.f32.tf32.tf32.f32 "
        "{%0,%1,%2,%3}, {%4,%5,%6,%7}, {%8,%9}, {%0,%1,%2,%3};"
        : "+f"(d0), "+f"(d1), "+f"(d2), "+f"(d3)
        : "r"(a0), "r"(a1), "r"(a2), "r"(a3), "r"(b0), "r"(b1));
}

// gelu exact, matching jax: 0.5 * x * (1 + erf(x / sqrt(2)))
__device__ __forceinline__ float gelu_exact(float t) {
    float u = __fdiv_rn(t, 1.41421356237309515f);
    float e = erff(u);
    return __fmul_rn(__fmul_rn(0.5f, t), __fadd_rn(1.0f, e));
}

// ---------------------------------------------------------------------------
// prep: build tf32 B-fragment codebook
__global__ void vq_prep_kernel(const float* __restrict__ cb) {
    int e = blockIdx.x * blockDim.x + threadIdx.x;   // 32*512 = 16384
    int lane = e & 31;
    int s = (e >> 5) & 7;
    int n = e >> 8;
    int code = n * 8 + (lane >> 2);
    int k0 = s * 8 + (lane & 3);
    u32 lo = cvt_tf32(cb[code * 64 + k0]);
    u32 hi = cvt_tf32(cb[code * 64 + k0 + 4]);
    g_cbf[e] = ((u64)hi << 32) | (u64)lo;
}

// ---------------------------------------------------------------------------
// Exact d2 for (token column zcol in slab, code): sequential-k fp32 chain.
__device__ __forceinline__ float exact_d2(const float* __restrict__ sm,
                                          const float* __restrict__ zcol,
                                          float zz, int code,
                                          const float* __restrict__ CB) {
    const float* cp = CB + code * 64;
    float dot = 0.f;
#pragma unroll 8
    for (int k = 0; k < 64; k++) dot = fmaf(zcol[k * TPB], __ldg(cp + k), dot);
    return __fadd_rn(__fsub_rn(zz, __fmul_rn(2.f, dot)), sm[OFF_CC + code]);
}
__device__ __forceinline__ u64 d2key(float d2e, int code) {
    u32 ob = __float_as_uint(d2e);
    ob = (ob & 0x80000000u) ? ~ob : (ob | 0x80000000u);
    return ((u64)ob << 32) | (u32)code;
}

// ---------------------------------------------------------------------------
// Encoder for one token: z[64] out. Bit-exact arithmetic (R5/R7/R8).
__device__ __forceinline__ void encode_token(
    float* sm, int tid, const float* __restrict__ X, int tok, float* z)
{
    const float inv128 = 0.0078125f;
    float xr[INDIM];
    const float* xp = X + (size_t)tok * INDIM;
#pragma unroll
    for (int i = 0; i < INDIM; i++) xr[i] = __ldg(xp + i);
    u64 xd[INDIM];
#pragma unroll
    for (int i = 0; i < INDIM; i++) xd[i] = pk2(xr[i], xr[i]);

    float sum = 0.f;
#pragma unroll 2
    for (int g = 0; g < 32; g++) {
        const ulonglong2* w0 = (const ulonglong2*)(sm + OFF_W1P + (2 * g) * 32);
        const ulonglong2* w1 = (const ulonglong2*)(sm + OFF_W1P + (2 * g + 1) * 32);
        u64 a0 = 0ull, a1 = 0ull;
#pragma unroll
        for (int ii = 0; ii < 7; ii++) {
            ulonglong2 u0 = w0[ii], u1 = w1[ii];
            a0 = f2fma(xd[2 * ii], u0.x, a0);
            a0 = f2fma(xd[2 * ii + 1], u0.y, a0);
            a1 = f2fma(xd[2 * ii], u1.x, a1);
            a1 = f2fma(xd[2 * ii + 1], u1.y, a1);
        }
        float h0, h1, h2, h3;
        up2(a0, h0, h1); up2(a1, h2, h3);
        h0 = __fadd_rn(h0, sm[OFF_EB1 + 4 * g + 0]);
        h1 = __fadd_rn(h1, sm[OFF_EB1 + 4 * g + 1]);
        h2 = __fadd_rn(h2, sm[OFF_EB1 + 4 * g + 2]);
        h3 = __fadd_rn(h3, sm[OFF_EB1 + 4 * g + 3]);
        sum = __fadd_rn(__fadd_rn(__fadd_rn(__fadd_rn(sum, h0), h1), h2), h3);
        sm[OFF_H + (4 * g + 0) * TPB + tid] = h0;
        sm[OFF_H + (4 * g + 1) * TPB + tid] = h1;
        sm[OFF_H + (4 * g + 2) * TPB + tid] = h2;
        sm[OFF_H + (4 * g + 3) * TPB + tid] = h3;
    }
    float mu = __fmul_rn(sum, inv128);
    float vs = 0.f;
#pragma unroll 4
    for (int j = 0; j < HID; j++) {
        float d = __fsub_rn(sm[OFF_H + j * TPB + tid], mu);
        vs = __fadd_rn(vs, __fmul_rn(d, d));
    }
    float var = __fmul_rn(vs, inv128);
    float rs = __fdiv_rn(1.0f, sqrtf(__fadd_rn(var, 1e-5f)));

    u64 zp[32];
#pragma unroll
    for (int t2 = 0; t2 < 32; t2++) zp[t2] = 0ull;
#pragma unroll 2
    for (int j = 0; j < HID; j++) {
        float h = sm[OFF_H + j * TPB + tid];
        float t = __fadd_rn(__fmul_rn(__fmul_rn(__fsub_rn(h, mu), rs), sm[OFF_LN1G + j]), sm[OFF_LN1B + j]);
        float gel = gelu_exact(t);
        u64 ag = pk2(gel, gel);
        const ulonglong2* wv = (const ulonglong2*)(sm + OFF_W2 + j * LATENT);
#pragma unroll
        for (int t2 = 0; t2 < 16; t2++) {
            ulonglong2 u = wv[t2];
            zp[2 * t2]     = f2fma(ag, u.x, zp[2 * t2]);
            zp[2 * t2 + 1] = f2fma(ag, u.y, zp[2 * t2 + 1]);
        }
    }
#pragma unroll
    for (int t2 = 0; t2 < 32; t2++) up2(zp[t2], z[2 * t2], z[2 * t2 + 1]);
#pragma unroll
    for (int k = 0; k < LATENT; k++) z[k] = __fadd_rn(z[k], sm[OFF_B2 + k]);
}

// ---------------------------------------------------------------------------
// Decoder for one token from z[64]; returns commit partial. Exact arithmetic.
__device__ __forceinline__ float decode_token(
    float* sm, int tid, const float* __restrict__ CB, int tok, int bidx,
    const float* z, float* __restrict__ out)
{
    const float inv128 = 0.0078125f;
    float qst[LATENT];
    float closs = 0.f;
    const float4* qp = (const float4*)(CB + (size_t)bidx * LATENT);
#pragma unroll
    for (int k4 = 0; k4 < 16; k4++) {
        float4 f = __ldg(qp + k4);
        float qv[4] = {f.x, f.y, f.z, f.w};
#pragma unroll
        for (int u = 0; u < 4; u++) {
            int k = 4 * k4 + u;
            float dqz = __fsub_rn(qv[u], z[k]);
            closs = __fadd_rn(closs, __fmul_rn(dqz, dqz));
            qst[k] = __fadd_rn(z[k], dqz);
        }
    }

    float sum = 0.f;
#pragma unroll 1
    for (int g = 0; g < 32; g++) {
        const ulonglong2* w0 = (const ulonglong2*)(sm + OFF_DW1P + (2 * g) * 128);
        const ulonglong2* w1 = (const ulonglong2*)(sm + OFF_DW1P + (2 * g + 1) * 128);
        u64 a0 = 0ull, a1 = 0ull;
#pragma unroll
        for (int kk = 0; kk < 32; kk++) {
            ulonglong2 u0 = w0[kk], u1 = w1[kk];
            u64 q0 = pk2(qst[2 * kk], qst[2 * kk]);
            u64 q1 = pk2(qst[2 * kk + 1], qst[2 * kk + 1]);
            a0 = f2fma(q0, u0.x, a0);
            a0 = f2fma(q1, u0.y, a0);
            a1 = f2fma(q0, u1.x, a1);
            a1 = f2fma(q1, u1.y, a1);
        }
        float h0, h1, h2, h3;
        up2(a0, h0, h1); up2(a1, h2, h3);
        h0 = __fadd_rn(h0, sm[OFF_DB1 + 4 * g + 0]);
        h1 = __fadd_rn(h1, sm[OFF_DB1 + 4 * g + 1]);
        h2 = __fadd_rn(h2, sm[OFF_DB1 + 4 * g + 2]);
        h3 = __fadd_rn(h3, sm[OFF_DB1 + 4 * g + 3]);
        sum = __fadd_rn(__fadd_rn(__fadd_rn(__fadd_rn(sum, h0), h1), h2), h3);
        sm[OFF_H + (4 * g + 0) * TPB + tid] = h0;
        sm[OFF_H + (4 * g + 1) * TPB + tid] = h1;
        sm[OFF_H + (4 * g + 2) * TPB + tid] = h2;
        sm[OFF_H + (4 * g + 3) * TPB + tid] = h3;
    }
    float mu2 = __fmul_rn(sum, inv128);
    float vs2 = 0.f;
#pragma unroll 4
    for (int j = 0; j < HID; j++) {
        float d = __fsub_rn(sm[OFF_H + j * TPB + tid], mu2);
        vs2 = __fadd_rn(vs2, __fmul_rn(d, d));
    }
    float var2 = __fmul_rn(vs2, inv128);
    float rs2 = __fdiv_rn(1.0f, sqrtf(__fadd_rn(var2, 1e-5f)));

    u64 op[7];
#pragma unroll
    for (int i = 0; i < 7; i++) op[i] = 0ull;
#pragma unroll 2
    for (int j = 0; j < HID; j++) {
        float h = sm[OFF_H + j * TPB + tid];
        float t = __fadd_rn(__fmul_rn(__fmul_rn(__fsub_rn(h, mu2), rs2), sm[OFF_LN2G + j]), sm[OFF_LN2B + j]);
        float gel = gelu_exact(t);
        u64 ag = pk2(gel, gel);
        const ulonglong2* rv = (const ulonglong2*)(sm + OFF_DW2T + j * 16);
        ulonglong2 u0 = rv[0], u1 = rv[1], u2 = rv[2], u3 = rv[3];
        op[0] = f2fma(ag, u0.x, op[0]);
        op[1] = f2fma(ag, u0.y, op[1]);
        op[2] = f2fma(ag, u1.x, op[2]);
        op[3] = f2fma(ag, u1.y, op[3]);
        op[4] = f2fma(ag, u2.x, op[4]);
        op[5] = f2fma(ag, u2.y, op[5]);
        op[6] = f2fma(ag, u3.x, op[6]);
    }
    float o[14];
#pragma unroll
    for (int i = 0; i < 7; i++) up2(op[i], o[2 * i], o[2 * i + 1]);
    float* opo = out + (size_t)tok * INDIM;
#pragma unroll
    for (int i = 0; i < INDIM; i++) opo[i] = __fadd_rn(o[i], sm[OFF_DB2 + i]);
    return closs;
}

// ---------------------------------------------------------------------------
__global__ void __launch_bounds__(TPB, 1)
vq_fused_kernel(const float* __restrict__ X,
                const float* __restrict__ EW1, const float* __restrict__ EB1,
                const float* __restrict__ L1G, const float* __restrict__ L1B,
                const float* __restrict__ EW2, const float* __restrict__ EB2,
                const float* __restrict__ CB,
                const float* __restrict__ DW1, const float* __restrict__ DB1,
                const float* __restrict__ L2G, const float* __restrict__ L2B,
                const float* __restrict__ DW2, const float* __restrict__ DB2,
                float* __restrict__ out) {
    extern __shared__ float sm[];
    int* sHist = (int*)(sm + OFF_HIST);

    const int tid  = threadIdx.x;
    const int wid  = tid >> 5;
    const int lane = tid & 31;
    const int g    = lane >> 2;     // groupID (row base)
    const int tig  = lane & 3;      // thread-in-group

    // ---- one-time block init ----
    for (int idx = tid; idx < 64 * 32; idx += TPB) {
        int p = idx >> 5, r = idx & 31, i = r >> 1, s = r & 1;
        sm[OFF_W1P + idx] = (i < INDIM) ? EW1[i * HID + 2 * p + s] : 0.f;
    }
    for (int i = tid; i < HID * LATENT; i += TPB) sm[OFF_W2 + i] = EW2[i];
    for (int idx = tid; idx < 64 * 128; idx += TPB) {
        int p = idx >> 7, r = idx & 127, k = r >> 1, s = r & 1;
        sm[OFF_DW1P + idx] = DW1[k * HID + 2 * p + s];
    }
    for (int i = tid; i < HID * INDIM; i += TPB) {
        int r = i / INDIM, c = i % INDIM;
        sm[OFF_DW2T + r * 16 + c] = DW2[i];
    }
    for (int i = tid; i < HID; i += TPB) { sm[OFF_DW2T + i * 16 + 14] = 0.f; sm[OFF_DW2T + i * 16 + 15] = 0.f; }
    for (int i = tid; i < HID; i += TPB) {
        sm[OFF_EB1 + i] = EB1[i]; sm[OFF_LN1G + i] = L1G[i]; sm[OFF_LN1B + i] = L1B[i];
        sm[OFF_DB1 + i] = DB1[i]; sm[OFF_LN2G + i] = L2G[i]; sm[OFF_LN2B + i] = L2B[i];
    }
    for (int i = tid; i < LATENT; i += TPB) sm[OFF_B2 + i] = EB2[i];
    for (int i = tid; i < 16; i += TPB) sm[OFF_DB2 + i] = (i < INDIM) ? DB2[i] : 0.f;
    for (int i = tid; i < KCODES; i += TPB) sHist[i] = 0;
    for (int c = tid; c < KCODES; c += TPB) {
        const float* p = CB + c * LATENT;
        float acc = 0.f;
#pragma unroll
        for (int k = 0; k < LATENT; k++) {
            float v = __ldg(p + k);
            acc = __fadd_rn(acc, __fmul_rn(v, v));
        }
        sm[OFF_CC + c] = acc;
    }
    __syncthreads();

    // max codebook norm (for tf32 error margin)
    float cn = 0.f;
    for (int i = 0; i < KCODES; i++) cn = fmaxf(cn, sm[OFF_CC + i]);
    const float cnmax = sqrtf(cn);

    // per-warp scratch (256 floats): [0:32) zz | [32:64) thr | [64:96) idxA | [96:128) cnt
    float* ZZp  = sm + OFF_CHUNK + wid * 256;
    float* THRp = ZZp + 32;
    int*   IDXp = (int*)(ZZp + 64);
    int*   CNTp = (int*)(ZZp + 96);
    // candidate lists: H rows 64..79, token column l of this warp
    #define LIST(i, l) (((int*)sm)[OFF_H + (64 + (i)) * TPB + wid * 32 + (l)])

    // ---- dynamic ticket loop: task = 32 tokens (token = lane) ----
    for (;;) {
        unsigned int t;
        if (lane == 0) t = atomicAdd(&g_ticket, 1u);
        t = __shfl_sync(0xffffffffu, t, 0);
        if (t >= NTASK) break;
        const int tok = (int)t * 32 + lane;

        // ---- encode; stash exact z into H rows 0..63 ----
        float z[LATENT];
        encode_token(sm, tid, X, tok, z);
        float zz = 0.f;
#pragma unroll
        for (int k = 0; k < LATENT; k++) zz = __fadd_rn(zz, __fmul_rn(z[k], z[k]));
#pragma unroll
        for (int k = 0; k < LATENT; k++) sm[OFF_H + k * TPB + tid] = z[k];
        ZZp[lane] = zz;
        CNTp[lane] = 0;
        __syncwarp();

        // ---- build tf32 A fragments from the warp's Z slab ----
        u32 A0[32], A1[32];
#pragma unroll
        for (int s = 0; s < 8; s++) {
            A0[4 * s + 0] = cvt_tf32(sm[OFF_H + (8 * s + tig) * TPB + wid * 32 + g]);
            A0[4 * s + 1] = cvt_tf32(sm[OFF_H + (8 * s + tig) * TPB + wid * 32 + g + 8]);
            A0[4 * s + 2] = cvt_tf32(sm[OFF_H + (8 * s + tig + 4) * TPB + wid * 32 + g]);
            A0[4 * s + 3] = cvt_tf32(sm[OFF_H + (8 * s + tig + 4) * TPB + wid * 32 + g + 8]);
            A1[4 * s + 0] = cvt_tf32(sm[OFF_H + (8 * s + tig) * TPB + wid * 32 + g + 16]);
            A1[4 * s + 1] = cvt_tf32(sm[OFF_H + (8 * s + tig) * TPB + wid * 32 + g + 24]);
            A1[4 * s + 2] = cvt_tf32(sm[OFF_H + (8 * s + tig + 4) * TPB + wid * 32 + g + 16]);
            A1[4 * s + 3] = cvt_tf32(sm[OFF_H + (8 * s + tig + 4) * TPB + wid * 32 + g + 24]);
        }
        float zzr[4] = { ZZp[g], ZZp[g + 8], ZZp[g + 16], ZZp[g + 24] };

        // ---- pass 1: approx sweep with best-2 tracking per row ----
        float bm[4]  = {3.4e38f, 3.4e38f, 3.4e38f, 3.4e38f};
        float bm2[4] = {3.4e38f, 3.4e38f, 3.4e38f, 3.4e38f};
        int   bix[4] = {0, 0, 0, 0};
        {
            u64 bc[8];
#pragma unroll
            for (int j = 0; j < 8; j++) bc[j] = __ldg((const u64*)g_cbf + j * 32 + lane);
#pragma unroll 1
            for (int n = 0; n < 64; n++) {
                u64 bn[8];
                if (n < 63) {
#pragma unroll
                    for (int j = 0; j < 8; j++)
                        bn[j] = __ldg((const u64*)g_cbf + (n + 1) * 256 + j * 32 + lane);
                }
                float d[8];
                d[0]=d[1]=d[2]=d[3]=d[4]=d[5]=d[6]=d[7]=0.f;
#pragma unroll
                for (int s = 0; s < 8; s++) {
                    u32 b0 = (u32)bc[s], b1 = (u32)(bc[s] >> 32);
                    mma_tf32(d[0], d[1], d[2], d[3], A0[4*s], A0[4*s+1], A0[4*s+2], A0[4*s+3], b0, b1);
                    mma_tf32(d[4], d[5], d[6], d[7], A1[4*s], A1[4*s+1], A1[4*s+2], A1[4*s+3], b0, b1);
                }
                float cc0 = sm[OFF_CC + 8 * n + 2 * tig];
                float cc1 = sm[OFF_CC + 8 * n + 2 * tig + 1];
                int c0 = 8 * n + 2 * tig;
#pragma unroll
                for (int r = 0; r < 4; r++) {
                    float e0 = zzr[r] - 2.f * d[2 * r] + cc0;
                    float e1 = zzr[r] - 2.f * d[2 * r + 1] + cc1;
                    if (e0 < bm[r]) { bm2[r] = bm[r]; bm[r] = e0; bix[r] = c0; }
                    else bm2[r] = fminf(bm2[r], e0);
                    if (e1 < bm[r]) { bm2[r] = bm[r]; bm[r] = e1; bix[r] = c0 + 1; }
                    else bm2[r] = fminf(bm2[r], e1);
                }
                if (n < 63) {
#pragma unroll
                    for (int j = 0; j < 8; j++) bc[j] = bn[j];
                }
            }
        }
        // quad merge of (m, idx, m2) triples
#pragma unroll
        for (int off = 1; off <= 2; off <<= 1) {
#pragma unroll
            for (int r = 0; r < 4; r++) {
                float om  = __shfl_xor_sync(0xffffffffu, bm[r],  off);
                float om2 = __shfl_xor_sync(0xffffffffu, bm2[r], off);
                int   oi  = __shfl_xor_sync(0xffffffffu, bix[r], off);
                if (om < bm[r]) { bm2[r] = fminf(bm[r], om2); bm[r] = om; bix[r] = oi; }
                else            { bm2[r] = fminf(bm2[r], om); }
            }
        }
        // per-row threshold + singleton test (tig==0 writes; rows g,g+8,g+16,g+24)
        bool anyNS = false;
        if (tig == 0) {
#pragma unroll
            for (int r = 0; r < 4; r++) {
                int row = g + 8 * r;
                float eps2 = __fadd_rn(__fmul_rn(__fmul_rn(0.00390625f, sqrtf(zzr[r])), cnmax), 2e-3f);
                float thr = __fadd_rn(bm[r], eps2);
                bool sing = (bm2[r] > thr);
                THRp[row] = sing ? -3.4e38f : thr;
                IDXp[row] = bix[r];
                anyNS |= !sing;
            }
        }
        bool need2 = __any_sync(0xffffffffu, anyNS);
        __syncwarp();

        // ---- pass 2 (rare-ish): push candidate codes per token ----
        if (need2) {
            float thrR[4] = { THRp[g], THRp[g + 8], THRp[g + 16], THRp[g + 24] };
            u64 bc[8];
#pragma unroll
            for (int j = 0; j < 8; j++) bc[j] = __ldg((const u64*)g_cbf + j * 32 + lane);
#pragma unroll 1
            for (int n = 0; n < 64; n++) {
                u64 bn[8];
                if (n < 63) {
#pragma unroll
                    for (int j = 0; j < 8; j++)
                        bn[j] = __ldg((const u64*)g_cbf + (n + 1) * 256 + j * 32 + lane);
                }
                float d[8];
                d[0]=d[1]=d[2]=d[3]=d[4]=d[5]=d[6]=d[7]=0.f;
#pragma unroll
                for (int s = 0; s < 8; s++) {
                    u32 b0 = (u32)bc[s], b1 = (u32)(bc[s] >> 32);
                    mma_tf32(d[0], d[1], d[2], d[3], A0[4*s], A0[4*s+1], A0[4*s+2], A0[4*s+3], b0, b1);
                    mma_tf32(d[4], d[5], d[6], d[7], A1[4*s], A1[4*s+1], A1[4*s+2], A1[4*s+3], b0, b1);
                }
                float cc0 = sm[OFF_CC + 8 * n + 2 * tig];
                float cc1 = sm[OFF_CC + 8 * n + 2 * tig + 1];
                int c0 = 8 * n + 2 * tig;
#pragma unroll
                for (int r = 0; r < 4; r++) {
                    int row = g + 8 * r;
                    float e0 = zzr[r] - 2.f * d[2 * r] + cc0;
                    float e1 = zzr[r] - 2.f * d[2 * r + 1] + cc1;
                    if (e0 <= thrR[r]) {
                        int pos = atomicAdd(&CNTp[row], 1);
                        if (pos < 16) LIST(pos, row) = c0;
                    }
                    if (e1 <= thrR[r]) {
                        int pos = atomicAdd(&CNTp[row], 1);
                        if (pos < 16) LIST(pos, row) = c0 + 1;
                    }
                }
                if (n < 63) {
#pragma unroll
                    for (int j = 0; j < 8; j++) bc[j] = bn[j];
                }
            }
            __syncwarp();
        }

        // ---- batched exact resolve: lane l owns token l ----
        int bidx;
        {
            int n = CNTp[lane];
            if (n == 0) {
                bidx = IDXp[lane];     // provably exact argmin
            } else {
                const float* zcol = sm + OFF_H + wid * 32 + lane;
                u64 kmin = 0xFFFFFFFFFFFFFFFFull;
                if (n <= 16) {
                    for (int i = 0; i < n; i++) {
                        int code = LIST(i, lane);
                        float d2e = exact_d2(sm, zcol, zz, code, CB);
                        u64 key = d2key(d2e, code);
                        kmin = (key < kmin) ? key : kmin;
                    }
                } else {
                    for (int code = 0; code < KCODES; code++) {
                        float d2e = exact_d2(sm, zcol, zz, code, CB);
                        u64 key = d2key(d2e, code);
                        kmin = (key < kmin) ? key : kmin;
                    }
                }
                bidx = (int)(kmin & 0xFFFFFFFFull);
            }
        }
        __syncwarp();

        atomicAdd(&sHist[bidx], 1);
        out[OUT_IDX_OFF + tok] = (float)bidx;

        // ---- reload exact z and decode ----
#pragma unroll
        for (int k = 0; k < LATENT; k++) z[k] = sm[OFF_H + k * TPB + tid];
        float cl = decode_token(sm, tid, CB, tok, bidx, z, out);

        // per-task deterministic commit partial (fixed shfl tree)
#pragma unroll
        for (int s = 16; s > 0; s >>= 1)
            cl = __fadd_rn(cl, __shfl_down_sync(0xffffffffu, cl, s));
        if (lane == 0) g_taskc[t] = cl;
    }

    // ---- merge histogram ----
    __syncthreads();
    for (int i = tid; i < KCODES; i += TPB) {
        int c = sHist[i];
        if (c) atomicAdd(&g_counts[i], c);
    }

    // ---- last-block finalize ----
    __threadfence();
    __shared__ unsigned int sTicket;
    if (tid == 0) sTicket = atomicAdd(&g_done, 1u);
    __syncthreads();
    if (sTicket == GRID_A - 1) {
        float* sRed = sm + OFF_CHUNK;
        float s16 = 0.f;
#pragma unroll
        for (int j = 0; j < 16; j++) s16 += g_taskc[tid * 16 + j];
        float p0 = (float)g_counts[tid] * (1.0f / (float)NTOK);
        float p1 = (float)g_counts[tid + 256] * (1.0f / (float)NTOK);
        float ent = p0 * logf(p0 + 1e-10f) + p1 * logf(p1 + 1e-10f);
        sRed[tid] = s16;
        sRed[256 + tid] = ent;
        __syncthreads();
#pragma unroll
        for (int s = 128; s > 0; s >>= 1) {
            if (tid < s) {
                sRed[tid] += sRed[tid + s];
                sRed[256 + tid] += sRed[256 + tid + s];
            }
            __syncthreads();
        }
        if (tid == 0) {
            out[OUT_COMMIT] = 0.25f * (sRed[0] / ((float)NTOK * (float)LATENT));
            out[OUT_PERP] = expf(-sRed[256]);
        }
        __syncthreads();
        for (int i = tid; i < KCODES; i += TPB) g_counts[i] = 0;
        if (tid == 0) { g_done = 0; g_ticket = 0; }
    }
}

// ---------------------------------------------------------------------------
extern "C" void kernel_launch(void* const* d_in, const int* in_sizes, int n_in,
                              void* d_out, int out_size) {
    const float* x    = (const float*)d_in[0];
    const float* ew1  = (const float*)d_in[1];
    const float* eb1  = (const float*)d_in[2];
    const float* l1g  = (const float*)d_in[3];
    const float* l1b  = (const float*)d_in[4];
    const float* ew2  = (const float*)d_in[5];
    const float* eb2  = (const float*)d_in[6];
    const float* cb   = (const float*)d_in[7];
    const float* dw1  = (const float*)d_in[8];
    const float* db1  = (const float*)d_in[9];
    const float* l2g  = (const float*)d_in[10];
    const float* l2b  = (const float*)d_in[11];
    const float* dw2  = (const float*)d_in[12];
    const float* db2  = (const float*)d_in[13];
    float* out = (float*)d_out;

    cudaFuncSetAttribute(vq_fused_kernel,
                         cudaFuncAttributeMaxDynamicSharedMemorySize, SMEM_BYTES);

    vq_prep_kernel<<<32, 512>>>(cb);
    vq_fused_kernel<<<GRID_A, TPB, SMEM_BYTES>>>(
        x, ew1, eb1, l1g, l1b, ew2, eb2, cb,
        dw1, db1, l2g, l2b, dw2, db2, out);
}